// round 7
// baseline (speedup 1.0000x reference)
#include <cuda_runtime.h>
#include <cstddef>

#define Bz 8
#define Tz 256
#define Uz 64
#define U1 65
#define BSTRIDE 66   // row stride for both normal and diagonal layouts (8B-aligned rows)
#define Vz 512
#define ND  320       // diagonal rows: d = t+u in [0, 319]
#define NEG 1e30f

#define LOG2E 1.4426950408889634f
#define LN2   0.6931471805599453f

// Scratch (device globals: allocation inside kernel_launch is forbidden)
__device__ float    g_blank[Bz * Tz * BSTRIDE];  // blank log2-prob, normal layout
__device__ float    g_emit [Bz * Tz * Uz];       // emit  log2-prob, normal layout
__device__ float    g_loss [Bz];                 // per-batch alpha_final+blank (log2)
__device__ unsigned g_done = 0;                  // last-CTA-reduces counter

__device__ __forceinline__ float ex2f(float x) {
    float r; asm("ex2.approx.ftz.f32 %0, %1;" : "=f"(r) : "f"(x)); return r;
}

// logaddexp in log2 domain: max(x,y) + log2(1 + 2^-|x-y|)
// log2(1+z) approximated by z*(c0 + c1 z + c2 z^2 + c3 z^3), Estrin form.
// Exact at z=0 -> logadd2(x, -1e30) == x (identity), which the padding relies on.
__device__ __forceinline__ float logadd2(float x, float y)
{
    const float m  = fmaxf(x, y);
    const float z  = ex2f(-fabsf(x - y));
    const float z2 = z * z;
    const float t1 = fmaf(-0.6701403f, z, 1.4362632f);
    const float t2 = fmaf(-0.0791604f, z, 0.3126861f);
    const float p  = fmaf(z2, t2, t1);
    return fmaf(z, p, m);
}

// ---------------------------------------------------------------------------
// Kernel 1: per-row logsumexp over V=512; writes blank/emit in LOG2 domain.
// One warp per (b,t,u) row. 272 MB streamed once -> HBM-bound (80% of peak).
// ---------------------------------------------------------------------------
__global__ void __launch_bounds__(256) lse_kernel(const float* __restrict__ pred,
                                                  const int* __restrict__ target)
{
    const int warp = (blockIdx.x * blockDim.x + threadIdx.x) >> 5;
    const int lane = threadIdx.x & 31;
    const int n_rows = Bz * Tz * U1;
    if (warp >= n_rows) return;

    const float* row = pred + (size_t)warp * Vz;

    float4 v[4];
    float mx = -1e30f;
#pragma unroll
    for (int c = 0; c < 4; c++) {
        v[c] = __ldcs(reinterpret_cast<const float4*>(row + c * 128 + lane * 4));
        mx = fmaxf(mx, fmaxf(fmaxf(v[c].x, v[c].y), fmaxf(v[c].z, v[c].w)));
    }
#pragma unroll
    for (int o = 16; o > 0; o >>= 1)
        mx = fmaxf(mx, __shfl_xor_sync(0xFFFFFFFFu, mx, o));

    float s = 0.0f;
#pragma unroll
    for (int c = 0; c < 4; c++) {
        s += __expf(v[c].x - mx) + __expf(v[c].y - mx)
           + __expf(v[c].z - mx) + __expf(v[c].w - mx);
    }
#pragma unroll
    for (int o = 16; o > 0; o >>= 1)
        s += __shfl_xor_sync(0xFFFFFFFFu, s, o);

    const float lse = mx + __logf(s);

    if (lane == 0) {
        const int b   = warp / (Tz * U1);
        const int rem = warp % (Tz * U1);
        const int t   = rem / U1;
        const int u   = rem % U1;
        g_blank[(b * Tz + t) * BSTRIDE + u] = (row[0] - lse) * LOG2E;  // blank_id = 0
        if (u < Uz) {
            const int tgt = target[b * Uz + u];
            g_emit[(b * Tz + t) * Uz + u] = (row[tgt] - lse) * LOG2E;
        }
    }
}

// ---------------------------------------------------------------------------
// Kernel 2: alpha DP in a single warp, pair mapping: lane l owns u=2l, 2l+1;
// u=64 computed uniformly on all lanes. Diagonal-major SMEM with identity
// padding (blank->0, emit->-1e30 outside the active trapezoid and for
// t >= pred_len) => ONE unguarded loop of 319 identical steps; at the end
// A[u] == alpha[t_last][u] for every u.
// ---------------------------------------------------------------------------
__global__ void __launch_bounds__(256) dp_kernel(const int* __restrict__ pred_len,
                                                 const int* __restrict__ target_len,
                                                 float* __restrict__ out)
{
    const int b   = blockIdx.x;
    const int tid = threadIdx.x;

    extern __shared__ float sm[];
    float* s_bd = sm;                   // ND * BSTRIDE  (blank, diagonal layout)
    float* s_ed = sm + ND * BSTRIDE;    // ND * BSTRIDE  (emit,  diagonal layout)
    __shared__ float s_e0[Uz];          // emit row t=0 (for row-0 cumsum)

    const int plen   = pred_len[b];     // [240, 256]
    const int tlen   = target_len[b];   // [56, 64]
    const int t_last = plen - 1;

    // ---- Pass 1: fill everything with identity values ----
    for (int i = tid; i < ND * BSTRIDE; i += 256) {
        s_bd[i] = 0.0f;
        s_ed[i] = -NEG;
    }
    __syncthreads();

    // ---- Pass 2: scatter valid (and length-masked) entries diagonally ----
    const float* gb = g_blank + b * Tz * BSTRIDE;
    const float* ge = g_emit  + b * Tz * Uz;

    // blank: update at (t,u) reads row t-1 -> identity (0) for t-1 >= t_last
    for (int i = tid; i < Tz * BSTRIDE; i += 256) {
        const int t = i / BSTRIDE;
        const int u = i - t * BSTRIDE;
        if (u < U1) {
            const float v = gb[i];
            s_bd[(t + u) * BSTRIDE + u] = (t >= t_last) ? 0.0f : v;
        }
    }
    // emit col u0 feeds dp column u=u0+1 at t_upd=t; identity for t<1 or t>t_last
    for (int i = tid; i < Tz * Uz; i += 256) {
        const int t  = i >> 6;
        const int u0 = i & 63;
        float v = ge[i];
        v = (t < 1 || t >= plen) ? -NEG : v;
        s_ed[(t + u0 + 1) * BSTRIDE + (u0 + 1)] = v;
    }
    if (tid < Uz) s_e0[tid] = ge[tid];  // t=0 row
    __syncthreads();

    if (tid >= 32) return;              // single-warp wavefront
    const int lane = tid;
    const bool is0 = (lane == 0);
    const unsigned FULL = 0xFFFFFFFFu;

    // ---- Row 0 init via warp-scan cumsum: row0[u] = sum e0[0..u-1] ----
    const float e0a = s_e0[2 * lane];
    const float e0b = s_e0[2 * lane + 1];
    const float pair = e0a + e0b;
    float scan = pair;
#pragma unroll
    for (int o = 1; o < 32; o <<= 1) {
        const float n = __shfl_up_sync(FULL, scan, o);
        scan += (lane >= o) ? n : 0.0f;
    }
    float A_e = scan - pair;            // alpha[0][2l]
    float A_o = A_e + e0a;              // alpha[0][2l+1]
    float A_t = __shfl_sync(FULL, scan, 31);   // alpha[0][64], uniform

    // ---- Main loop: 319 identical, unguarded steps ----
    int rb = 0;                         // (d-1)*BSTRIDE
#pragma unroll 4
    for (int d = 1; d < ND; d++) {
        const float prev_o = __shfl_up_sync(FULL, A_o, 1);   // alpha[.][2l-1]
        const float o31    = __shfl_sync(FULL, A_o, 31);     // alpha[.][63]

        const float2 bd = *reinterpret_cast<const float2*>(s_bd + rb + 2 * lane);
        const float2 ed = *reinterpret_cast<const float2*>(s_ed + rb + BSTRIDE + 2 * lane);
        const float bdt = s_bd[rb + Uz];                     // col 64 (broadcast)
        const float edt = s_ed[rb + BSTRIDE + Uz];

        const float xe = A_e + bd.x;
        const float ye = is0 ? -NEG : (prev_o + ed.x);
        const float xo = A_o + bd.y;
        const float yo = A_e + ed.y;                         // uses OLD A_e
        const float xt = A_t + bdt;
        const float yt = o31 + edt;

        A_e = logadd2(xe, ye);
        A_o = logadd2(xo, yo);
        A_t = logadd2(xt, yt);

        rb += BSTRIDE;
    }

    // ---- Extract alpha[t_last][tlen] ----
    const int sel = (tlen >> 1) & 31;
    const float vE = __shfl_sync(FULL, A_e, sel);
    const float vO = __shfl_sync(FULL, A_o, sel);
    const float fa = (tlen == Uz) ? A_t : ((tlen & 1) ? vO : vE);

    if (is0) {
        const float fb = gb[t_last * BSTRIDE + tlen];        // blank2[t_last][tlen]
        g_loss[b] = fa + fb;                                 // log2 domain
        __threadfence();
        const unsigned n = atomicAdd(&g_done, 1);
        if (n == Bz - 1) {
            __threadfence();
            float s = 0.0f;
#pragma unroll
            for (int i = 0; i < Bz; i++)
                s += ((volatile float*)g_loss)[i];
            out[0] = -s * (LN2 / Bz);
            g_done = 0;                 // reset for next graph replay
        }
    }
}

extern "C" void kernel_launch(void* const* d_in, const int* in_sizes, int n_in,
                              void* d_out, int out_size)
{
    const float* pred       = (const float*)d_in[0];  // (B,T,U+1,V) fp32
    const int*   target     = (const int*)  d_in[1];  // (B,U)
    const int*   pred_len   = (const int*)  d_in[2];  // (B,)
    const int*   target_len = (const int*)  d_in[3];  // (B,)
    float*       out        = (float*)d_out;

    const int n_rows = Bz * Tz * U1;                  // 133120 rows
    const int blocks = (n_rows + 7) / 8;              // 8 warps / block
    lse_kernel<<<blocks, 256>>>(pred, target);

    const int smem_bytes = 2 * ND * BSTRIDE * (int)sizeof(float);  // 168960 B
    cudaFuncSetAttribute(dp_kernel, cudaFuncAttributeMaxDynamicSharedMemorySize,
                         smem_bytes);
    dp_kernel<<<Bz, 256, smem_bytes>>>(pred_len, target_len, out);
}

// round 8
// speedup vs baseline: 1.0952x; 1.0952x over previous
#include <cuda_runtime.h>
#include <cstddef>

#define Bz 8
#define Tz 256
#define Uz 64
#define U1 65
#define BSTRIDE 66    // diagonal-row stride (odd delta -> conflict-free, 8B rows)
#define Vz 512
#define ND  320       // diagonal rows: d = t+u in [0, 319]
#define NDB (ND * BSTRIDE)   // 21120 floats per (batch, array)
#define NEG 1e30f

#define LOG2E 1.4426950408889634f
#define LN2   0.6931471805599453f

// Scratch (device globals: allocation inside kernel_launch is forbidden)
// Diagonal-layout, per-batch, identity-padded blank/emit log2-probs:
__device__ float    g_bd[Bz * NDB];     // blank: slot (t+u, u)      <- (t,u)
__device__ float    g_ed[Bz * NDB];     // emit : slot (t+u+1, u+1)  <- (t,u0)
__device__ float    g_fb[Bz * U1];      // true blank2[t_last][u]
__device__ float    g_e0[Bz * Uz];      // true emit2[0][u]
__device__ float    g_loss[Bz];
__device__ unsigned g_done = 0;

__device__ __forceinline__ float ex2f(float x) {
    float r; asm("ex2.approx.ftz.f32 %0, %1;" : "=f"(r) : "f"(x)); return r;
}

// logaddexp in log2 domain: max(x,y) + log2(1 + 2^-|x-y|), Estrin poly.
// Exact at z=0 -> logadd2(x, -1e30) == x (identity), which the padding relies on.
__device__ __forceinline__ float logadd2(float x, float y)
{
    const float m  = fmaxf(x, y);
    const float z  = ex2f(-fabsf(x - y));
    const float z2 = z * z;
    const float t1 = fmaf(-0.6701403f, z, 1.4362632f);
    const float t2 = fmaf(-0.0791604f, z, 0.3126861f);
    const float p  = fmaf(z2, t2, t1);
    return fmaf(z, p, m);
}

// ---------------------------------------------------------------------------
// Kernel 0: identity background for the diagonal arrays (blank=0, emit=-1e30).
// Slots inside the valid trapezoid are overwritten by lse_kernel afterwards.
// ---------------------------------------------------------------------------
__global__ void __launch_bounds__(256) init_kernel()
{
    const int i = blockIdx.x * 256 + threadIdx.x;       // float4 index
    if (i < Bz * NDB / 4) {
        reinterpret_cast<float4*>(g_bd)[i] = make_float4(0.f, 0.f, 0.f, 0.f);
        reinterpret_cast<float4*>(g_ed)[i] = make_float4(-NEG, -NEG, -NEG, -NEG);
    }
}

// ---------------------------------------------------------------------------
// Kernel 1: per-row logsumexp over V=512 (one warp per (b,t,u) row, HBM-bound).
// Writes blank/emit DIRECTLY in diagonal layout with length-masking baked in.
// ---------------------------------------------------------------------------
__global__ void __launch_bounds__(256) lse_kernel(const float* __restrict__ pred,
                                                  const int* __restrict__ target,
                                                  const int* __restrict__ pred_len)
{
    const int warp = (blockIdx.x * blockDim.x + threadIdx.x) >> 5;
    const int lane = threadIdx.x & 31;
    const int n_rows = Bz * Tz * U1;
    if (warp >= n_rows) return;

    const float* row = pred + (size_t)warp * Vz;

    float4 v[4];
    float mx = -1e30f;
#pragma unroll
    for (int c = 0; c < 4; c++) {
        v[c] = __ldcs(reinterpret_cast<const float4*>(row + c * 128 + lane * 4));
        mx = fmaxf(mx, fmaxf(fmaxf(v[c].x, v[c].y), fmaxf(v[c].z, v[c].w)));
    }
#pragma unroll
    for (int o = 16; o > 0; o >>= 1)
        mx = fmaxf(mx, __shfl_xor_sync(0xFFFFFFFFu, mx, o));

    float s = 0.0f;
#pragma unroll
    for (int c = 0; c < 4; c++) {
        s += __expf(v[c].x - mx) + __expf(v[c].y - mx)
           + __expf(v[c].z - mx) + __expf(v[c].w - mx);
    }
#pragma unroll
    for (int o = 16; o > 0; o >>= 1)
        s += __shfl_xor_sync(0xFFFFFFFFu, s, o);

    const float lse = mx + __logf(s);

    if (lane == 0) {
        const int b   = warp / (Tz * U1);
        const int rem = warp % (Tz * U1);
        const int t   = rem / U1;
        const int u   = rem % U1;
        const int plen   = pred_len[b];
        const int t_last = plen - 1;

        const float vb = (row[0] - lse) * LOG2E;            // blank_id = 0
        // Loop only consumes blank[t-1] for updates at t <= t_last; freeze after.
        g_bd[b * NDB + (t + u) * BSTRIDE + u] = (t >= t_last) ? 0.0f : vb;
        if (t == t_last) g_fb[b * U1 + u] = vb;             // true value for loss

        if (u < Uz) {
            const int tgt = target[b * Uz + u];
            const float ve = (row[tgt] - lse) * LOG2E;
            // emit col u feeds dp column u+1 at update time t; mask t<1, t>t_last.
            g_ed[b * NDB + (t + u + 1) * BSTRIDE + (u + 1)] =
                (t < 1 || t >= plen) ? -NEG : ve;
            if (t == 0) g_e0[b * Uz + u] = ve;              // row-0 cumsum input
        }
    }
}

// ---------------------------------------------------------------------------
// Kernel 2: alpha DP in a single warp. Lane l owns u=2l, 2l+1; u=64 uniform.
// Staging is a pure float4 memcpy of the pre-diagonalized, pre-masked arrays.
// Main loop: 319 identical unguarded steps; self-chain ~40cyc/step, the shfl
// edge is feed-forward in lane index so it never binds steady state.
// ---------------------------------------------------------------------------
__global__ void __launch_bounds__(256) dp_kernel(const int* __restrict__ target_len,
                                                 float* __restrict__ out)
{
    const int b   = blockIdx.x;
    const int tid = threadIdx.x;

    extern __shared__ float sm[];
    float* s_bd = sm;            // NDB floats
    float* s_ed = sm + NDB;      // NDB floats

    // Stage both diagonal arrays (169 KB) as float4 memcpy.
    {
        const float4* gb = reinterpret_cast<const float4*>(g_bd + b * NDB);
        const float4* ge = reinterpret_cast<const float4*>(g_ed + b * NDB);
        float4* sb = reinterpret_cast<float4*>(s_bd);
        float4* se = reinterpret_cast<float4*>(s_ed);
#pragma unroll 4
        for (int i = tid; i < NDB / 4; i += 256) {
            sb[i] = gb[i];
            se[i] = ge[i];
        }
    }
    __syncthreads();

    if (tid >= 32) return;       // single-warp wavefront
    const int lane = tid;
    const unsigned FULL = 0xFFFFFFFFu;
    const int tlen = target_len[b];   // [56, 64]

    // ---- Row 0 init via warp-scan cumsum of emit[0][.] ----
    const float e0a = __ldg(&g_e0[b * Uz + 2 * lane]);
    const float e0b = __ldg(&g_e0[b * Uz + 2 * lane + 1]);
    const float pair = e0a + e0b;
    float scan = pair;
#pragma unroll
    for (int o = 1; o < 32; o <<= 1) {
        const float n = __shfl_up_sync(FULL, scan, o);
        scan += (lane >= o) ? n : 0.0f;
    }
    float A_e = scan - pair;                   // alpha[0][2l]
    float A_o = A_e + e0a;                     // alpha[0][2l+1]
    float A_t = __shfl_sync(FULL, scan, 31);   // alpha[0][64], uniform

    // ---- Main loop: 319 identical, unguarded steps ----
    // Column u=0's emit slot is never written -> -1e30 -> logadd2 identity,
    // so no lane-0 special case is needed anywhere.
    int rb = 0;                                // (d-1)*BSTRIDE
#pragma unroll 4
    for (int d = 1; d < ND; d++) {
        const float prev_o = __shfl_up_sync(FULL, A_o, 1);   // alpha[.][2l-1]
        const float o31    = __shfl_sync(FULL, A_o, 31);     // alpha[.][63]

        const float2 bd = *reinterpret_cast<const float2*>(s_bd + rb + 2 * lane);
        const float2 ed = *reinterpret_cast<const float2*>(s_ed + rb + BSTRIDE + 2 * lane);
        const float bdt = s_bd[rb + Uz];                     // col 64 (broadcast)
        const float edt = s_ed[rb + BSTRIDE + Uz];

        const float xe = A_e + bd.x;
        const float ye = prev_o + ed.x;        // lane0: ed.x = -1e30 -> identity
        const float xo = A_o + bd.y;
        const float yo = A_e + ed.y;           // uses OLD A_e
        const float xt = A_t + bdt;
        const float yt = o31 + edt;

        A_e = logadd2(xe, ye);
        A_o = logadd2(xo, yo);
        A_t = logadd2(xt, yt);

        rb += BSTRIDE;
    }

    // ---- Extract alpha[t_last][tlen] (updates past t_last were frozen) ----
    const int sel = (tlen >> 1) & 31;
    const float vE = __shfl_sync(FULL, A_e, sel);
    const float vO = __shfl_sync(FULL, A_o, sel);
    const float fa = (tlen == Uz) ? A_t : ((tlen & 1) ? vO : vE);

    if (lane == 0) {
        const float fb = __ldg(&g_fb[b * U1 + tlen]);        // true blank2[t_last][tlen]
        g_loss[b] = fa + fb;                                 // log2 domain
        __threadfence();
        const unsigned n = atomicAdd(&g_done, 1);
        if (n == Bz - 1) {
            __threadfence();
            float s = 0.0f;
#pragma unroll
            for (int i = 0; i < Bz; i++)
                s += ((volatile float*)g_loss)[i];
            out[0] = -s * (LN2 / Bz);
            g_done = 0;                        // reset for next graph replay
        }
    }
}

extern "C" void kernel_launch(void* const* d_in, const int* in_sizes, int n_in,
                              void* d_out, int out_size)
{
    const float* pred       = (const float*)d_in[0];  // (B,T,U+1,V) fp32
    const int*   target     = (const int*)  d_in[1];  // (B,U)
    const int*   pred_len   = (const int*)  d_in[2];  // (B,)
    const int*   target_len = (const int*)  d_in[3];  // (B,)
    float*       out        = (float*)d_out;

    // Kernel 0: identity background (1.35 MB, trivial).
    const int init_blocks = (Bz * NDB / 4 + 255) / 256;     // 165
    init_kernel<<<init_blocks, 256>>>();

    // Kernel 1: logsumexp + diagonal scatter. 8 warps / block.
    const int n_rows = Bz * Tz * U1;                        // 133120 rows
    const int blocks = (n_rows + 7) / 8;
    lse_kernel<<<blocks, 256>>>(pred, target, pred_len);

    // Kernel 2: wavefront DP + fused mean.
    const int smem_bytes = 2 * NDB * (int)sizeof(float);    // 168960 B
    cudaFuncSetAttribute(dp_kernel, cudaFuncAttributeMaxDynamicSharedMemorySize,
                         smem_bytes);
    dp_kernel<<<Bz, 256, smem_bytes>>>(target_len, out);
}